// round 17
// baseline (speedup 1.0000x reference)
#include <cuda_runtime.h>
#include <cuda_fp16.h>
#include <math.h>
#include <cstdint>

#define NNODES 2048
#define BB 32
#define TT 12
#define DD 10
#define HH 32
#define CIN 33      // C + H
#define GOUT 64     // 2H
#define UOUT 32     // H
#define WG_SZ (2*CIN*GOUT)   // 4224
#define WU_SZ (2*CIN*UOUT)   // 2112
#define SBH (BB*HH)          // 1024 columns in state GEMM
#define XCOLS (TT*BB)        // 384
#define ASCALE 2048.0f
#define AINV   (1.0f/2048.0f)
#define KSPLIT 2

// ---------------- device scratch (static, no allocation) ----------------
__device__ __half g_Ahi[NNODES*NNODES];
__device__ __half g_Alo[NNODES*NNODES];
__device__ __half g_XT[XCOLS*NNODES];
__device__ __half g_ST[SBH*NNODES];
__device__ __half g_ZT[SBH*NNODES];
__device__ float g_Wg[NNODES*WG_SZ];
__device__ float g_Wu[NNODES*WU_SZ];
__device__ float g_bg[NNODES*GOUT];
__device__ float g_bu[NNODES*UOUT];
__device__ float g_Xprop[KSPLIT*NNODES*XCOLS];
__device__ float g_state[NNODES*SBH];
__device__ float g_P[KSPLIT*NNODES*SBH];
__device__ float g_zs[NNODES*SBH];
__device__ float g_P2[KSPLIT*NNODES*SBH];
__device__ float g_r[NNODES*SBH];

__device__ __forceinline__ uint32_t smem_u32(const void* p) {
    uint32_t a;
    asm("{ .reg .u64 t; cvta.to.shared.u64 t, %1; cvt.u32.u64 %0, t; }"
        : "=r"(a) : "l"(p));
    return a;
}
__device__ __forceinline__ void cp16(uint32_t s, const void* g) {
    asm volatile("cp.async.cg.shared.global [%0], [%1], 16;" :: "r"(s), "l"(g));
}
#define CP_COMMIT() asm volatile("cp.async.commit_group;" ::: "memory")
#define CP_WAIT1()  asm volatile("cp.async.wait_group 1;" ::: "memory")

// ---------------- ALU-only transcendentals (no MUFU) ----------------
__device__ __forceinline__ float fast_exp2(float t) {
    t = fminf(fmaxf(t, -126.0f), 126.0f);
    float z = t + 12582912.0f;
    int   nn = __float_as_int(z) - 0x4B400000;
    float fl = z - 12582912.0f;
    float f  = t - fl;
    float p = 1.0f + f*(0.6931472f + f*(0.24022651f + f*(0.05550411f
              + f*(0.00961813f + f*0.00133336f))));
    return __int_as_float(__float_as_int(p) + (nn << 23));
}
__device__ __forceinline__ float fast_rcp(float d) {
    float inv = __int_as_float(0x7EF311C3 - __float_as_int(d));
    inv = inv * (2.0f - d * inv);
    inv = inv * (2.0f - d * inv);
    inv = inv * (2.0f - d * inv);
    return inv;
}
__device__ __forceinline__ float fast_sigmoid(float x) {
    float r = fast_exp2(x * 1.4426950408889634f);
    return r * fast_rcp(1.0f + r);
}
__device__ __forceinline__ float fast_tanh(float x) {
    float r = fast_exp2(x * 2.8853900817779268f);
    return (r - 1.0f) * fast_rcp(r + 1.0f);
}

// ---------------- A = softmax(relu(E E^T)) row-wise, scaled fp16 hi/lo ---------
__global__ __launch_bounds__(256) void compute_A(const float* __restrict__ E) {
    int n = blockIdx.x;
    __shared__ float row[NNODES];
    __shared__ float red[256];
    __shared__ float en[DD];
    int tid = threadIdx.x;
    if (tid < DD) en[tid] = E[n*DD + tid];
    __syncthreads();
    float lmax = -1e30f;
    for (int m = tid; m < NNODES; m += 256) {
        float s = 0.f;
        #pragma unroll
        for (int d = 0; d < DD; d++) s += en[d] * E[m*DD + d];
        s = fmaxf(s, 0.f);
        row[m] = s;
        lmax = fmaxf(lmax, s);
    }
    red[tid] = lmax; __syncthreads();
    for (int s = 128; s > 0; s >>= 1) {
        if (tid < s) red[tid] = fmaxf(red[tid], red[tid+s]);
        __syncthreads();
    }
    float mx = red[0];
    __syncthreads();
    float lsum = 0.f;
    for (int m = tid; m < NNODES; m += 256) {
        float e = expf(row[m] - mx);
        row[m] = e;
        lsum += e;
    }
    red[tid] = lsum; __syncthreads();
    for (int s = 128; s > 0; s >>= 1) {
        if (tid < s) red[tid] += red[tid+s];
        __syncthreads();
    }
    float inv = ASCALE / red[0];
    for (int m = tid; m < NNODES; m += 256) {
        float v = row[m] * inv;
        __half h = __float2half_rn(v);
        g_Ahi[(size_t)n*NNODES + m] = h;
        g_Alo[(size_t)n*NNODES + m] = __float2half_rn(v - __half2float(h));
    }
}

// ---------------- node-specific weights from embedding pools ----------------
__global__ __launch_bounds__(256) void compute_node_weights(
    const float* __restrict__ E,
    const float* __restrict__ gW, const float* __restrict__ gb,
    const float* __restrict__ uW, const float* __restrict__ ub) {
    int n = blockIdx.x, tid = threadIdx.x;
    __shared__ float en[DD];
    if (tid < DD) en[tid] = E[n*DD + tid];
    __syncthreads();
    for (int j = tid; j < WG_SZ; j += 256) {
        float a = 0.f;
        #pragma unroll
        for (int d = 0; d < DD; d++) a += en[d] * gW[d*WG_SZ + j];
        g_Wg[(size_t)n*WG_SZ + j] = a;
    }
    for (int j = tid; j < WU_SZ; j += 256) {
        float a = 0.f;
        #pragma unroll
        for (int d = 0; d < DD; d++) a += en[d] * uW[d*WU_SZ + j];
        g_Wu[(size_t)n*WU_SZ + j] = a;
    }
    if (tid < GOUT) {
        float a = 0.f;
        #pragma unroll
        for (int d = 0; d < DD; d++) a += en[d] * gb[d*GOUT + tid];
        g_bg[n*GOUT + tid] = a;
    } else if (tid < GOUT + UOUT) {
        int j = tid - GOUT;
        float a = 0.f;
        #pragma unroll
        for (int d = 0; d < DD; d++) a += en[d] * ub[d*UOUT + j];
        g_bu[n*UOUT + j] = a;
    }
}

// ---------------- source -> X^T fp16  [j = t*B+b][node] ----------------
__global__ __launch_bounds__(256) void convert_xsrc(const float* __restrict__ src) {
    int idx = blockIdx.x * blockDim.x + threadIdx.x;
    if (idx >= XCOLS*NNODES) return;
    int j = idx >> 11;
    int n = idx & 2047;
    int t = j >> 5;
    int b = j & 31;
    g_XT[idx] = __float2half_rn(src[((size_t)b*TT + t)*NNODES + n]);
}

__global__ __launch_bounds__(256) void init_state() {
    int idx = blockIdx.x * blockDim.x + threadIdx.x;
    if (idx < NNODES*SBH) g_state[idx] = 0.f;
    if (idx < KSPLIT*NNODES*SBH) {
        g_P[idx] = 0.f;     // t=0: A @ 0 = 0 (GEMM skipped)
        g_P2[idx] = 0.f;    // t=0: A @ (z*0) = 0 (GEMM skipped)
    }
}

// ---------------- fp16 2-term GEMM, 128x128 tile, 3-stage cp.async pipeline ----
// (R14-proven config: SPAD=40 -> 80B row stride, multiple of 16B as required
//  by cp.async.16 / ldmatrix. SPAD=36 in R16 broke alignment.)
#define BK 32
#define SPAD 40
#define OFF_AH 0
#define OFF_AL (128*SPAD*2)
#define OFF_B  (2*128*SPAD*2)
#define BUFSZ  (3*128*SPAD*2)        // 30720 per stage
#define SM_TOTAL (3*BUFSZ)           // 92160, 3 stages, 2 blocks/SM

__device__ __forceinline__ void mma16816(float* c, const uint32_t* a, const uint32_t* b) {
    asm volatile(
        "mma.sync.aligned.m16n8k16.row.col.f32.f16.f16.f32 "
        "{%0,%1,%2,%3}, {%4,%5,%6,%7}, {%8,%9}, {%0,%1,%2,%3};"
        : "+f"(c[0]), "+f"(c[1]), "+f"(c[2]), "+f"(c[3])
        : "r"(a[0]), "r"(a[1]), "r"(a[2]), "r"(a[3]), "r"(b[0]), "r"(b[1]));
}
__device__ __forceinline__ void ldmx4(uint32_t* r, uint32_t addr) {
    asm volatile("ldmatrix.sync.aligned.m8n8.x4.shared.b16 {%0,%1,%2,%3}, [%4];"
                 : "=r"(r[0]), "=r"(r[1]), "=r"(r[2]), "=r"(r[3]) : "r"(addr));
}

__global__ __launch_bounds__(256, 2) void mma_gemm(
    const __half* __restrict__ Ahi, const __half* __restrict__ Alo,
    const __half* __restrict__ B,
    float* __restrict__ C, int ncols) {
    extern __shared__ char dsm[];
    uint32_t sb = smem_u32(dsm);
    int tid = threadIdx.x;
    int warp = tid >> 5, lane = tid & 31;
    int wm = (warp & 3) * 32;
    int wn = (warp >> 2) * 64;
    int m0 = blockIdx.y * 128;
    int n0 = blockIdx.x * 128;
    int kz = blockIdx.z;
    const int NKP = (NNODES/BK)/KSPLIT;   // 32 k-tiles per slab
    int kbeg = kz * NKP;
    float* Cp = C + (size_t)kz * NNODES * ncols;

    int l_r = tid >> 2, l_kc = (tid & 3) * 8;

    float acc[2][8][4];
    #pragma unroll
    for (int i = 0; i < 2; i++)
        #pragma unroll
        for (int j = 0; j < 8; j++)
            #pragma unroll
            for (int q = 0; q < 4; q++) acc[i][j][q] = 0.f;

    int a_r = lane & 15, a_k = (lane >> 4) * 8;
    int b_r = (lane & 7) + ((lane >> 4) & 1) * 8, b_k = ((lane >> 3) & 1) * 8;

    #define ISSUE_TILE(kt, buf) do {                                              \
        int _k0 = (kt) * BK;                                                      \
        uint32_t _b = sb + (buf) * BUFSZ;                                         \
        size_t _ga0 = (size_t)(m0 + l_r) * NNODES + _k0 + l_kc;                   \
        size_t _ga1 = (size_t)(m0 + l_r + 64) * NNODES + _k0 + l_kc;              \
        cp16(_b + OFF_AH + (l_r*SPAD + l_kc)*2,        Ahi + _ga0);               \
        cp16(_b + OFF_AH + ((l_r+64)*SPAD + l_kc)*2,   Ahi + _ga1);               \
        cp16(_b + OFF_AL + (l_r*SPAD + l_kc)*2,        Alo + _ga0);               \
        cp16(_b + OFF_AL + ((l_r+64)*SPAD + l_kc)*2,   Alo + _ga1);               \
        size_t _gb0 = (size_t)(n0 + l_r) * NNODES + _k0 + l_kc;                   \
        size_t _gb1 = (size_t)(n0 + l_r + 64) * NNODES + _k0 + l_kc;              \
        cp16(_b + OFF_B + (l_r*SPAD + l_kc)*2,         B + _gb0);                 \
        cp16(_b + OFF_B + ((l_r+64)*SPAD + l_kc)*2,    B + _gb1);                 \
        CP_COMMIT();                                                              \
    } while (0)

    ISSUE_TILE(kbeg + 0, 0);
    ISSUE_TILE(kbeg + 1, 1);

    int st = 0;
    for (int kt = 0; kt < NKP; kt++) {
        CP_WAIT1();
        __syncthreads();

        uint32_t bb = sb + st * BUFSZ;
        #pragma unroll
        for (int ks = 0; ks < BK; ks += 16) {
            uint32_t ah[2][4], al[2][4];
            #pragma unroll
            for (int mt = 0; mt < 2; mt++) {
                uint32_t ra = bb + OFF_AH + ((wm + mt*16 + a_r)*SPAD + ks + a_k)*2;
                ldmx4(ah[mt], ra);
                ldmx4(al[mt], ra + (OFF_AL - OFF_AH));
            }
            uint32_t bh[8][2];
            #pragma unroll
            for (int g = 0; g < 4; g++) {
                uint32_t rb = bb + OFF_B + ((wn + g*16 + b_r)*SPAD + ks + b_k)*2;
                uint32_t r4[4];
                ldmx4(r4, rb);
                bh[2*g][0] = r4[0]; bh[2*g][1] = r4[1];
                bh[2*g+1][0] = r4[2]; bh[2*g+1][1] = r4[3];
            }
            #pragma unroll
            for (int mt = 0; mt < 2; mt++)
                #pragma unroll
                for (int nt = 0; nt < 8; nt++) {
                    mma16816(acc[mt][nt], ah[mt], bh[nt]);
                    mma16816(acc[mt][nt], al[mt], bh[nt]);
                }
        }

        if (kt + 2 < NKP) {
            int s2 = st + 2; if (s2 >= 3) s2 -= 3;
            ISSUE_TILE(kbeg + kt + 2, s2);
        } else {
            CP_COMMIT();
        }
        if (++st == 3) st = 0;
    }

    #pragma unroll
    for (int mt = 0; mt < 2; mt++) {
        int row0 = m0 + wm + mt*16 + (lane >> 2);
        #pragma unroll
        for (int nt = 0; nt < 8; nt++) {
            int col = n0 + wn + nt*8 + (lane & 3)*2;
            *(float2*)(Cp + (size_t)row0*ncols + col) =
                make_float2(acc[mt][nt][0]*AINV, acc[mt][nt][1]*AINV);
            *(float2*)(Cp + (size_t)(row0+8)*ncols + col) =
                make_float2(acc[mt][nt][2]*AINV, acc[mt][nt][3]*AINV);
        }
    }
}

// ---------------- gate: one warp per node, 8b x 8o per thread ----------------
__global__ __launch_bounds__(32) void gate_kernel(const float* __restrict__ src, int t) {
    int n = blockIdx.x, lane = threadIdx.x;
    __shared__ float Wg_s[WG_SZ];
    __shared__ float bg_s[GOUT];
    __shared__ float st_s[HH*33];
    __shared__ float P_s[HH*33];
    __shared__ float x_s[BB], xp_s[BB];

    const float4* Wg4 = (const float4*)(g_Wg + (size_t)n*WG_SZ);
    for (int j = lane; j < WG_SZ/4; j += 32) ((float4*)Wg_s)[j] = Wg4[j];
    bg_s[lane]      = g_bg[n*GOUT + lane];
    bg_s[lane + 32] = g_bg[n*GOUT + lane + 32];
    for (int j = lane; j < SBH; j += 32) {
        int b = j >> 5, idx = j & 31;
        st_s[idx*33 + b] = g_state[(size_t)n*SBH + j];
        float p = 0.f;
        #pragma unroll
        for (int z = 0; z < KSPLIT; z++) p += g_P[((size_t)z*NNODES + n)*SBH + j];
        P_s[idx*33 + b] = p;
    }
    x_s[lane] = src[((size_t)lane*TT + t)*NNODES + n];
    {
        float xp = 0.f;
        #pragma unroll
        for (int z = 0; z < KSPLIT; z++)
            xp += g_Xprop[((size_t)z*NNODES + n)*XCOLS + t*BB + lane];
        xp_s[lane] = xp;
    }
    __syncwarp();

    int bg = lane >> 3, og = lane & 7;
    int b0 = bg*8, o0 = og*8;
    float acc[8][8];
    float w0[8], w1[8];
    #pragma unroll
    for (int oj = 0; oj < 8; oj++) {
        w0[oj] = Wg_s[o0 + oj];
        w1[oj] = Wg_s[CIN*GOUT + o0 + oj];
    }
    #pragma unroll
    for (int bi = 0; bi < 8; bi++) {
        float xv = x_s[b0+bi], xpv = xp_s[b0+bi];
        #pragma unroll
        for (int oj = 0; oj < 8; oj++)
            acc[bi][oj] = bg_s[o0+oj] + xv*w0[oj] + xpv*w1[oj];
    }
    for (int h = 0; h < HH; h++) {
        #pragma unroll
        for (int oj = 0; oj < 8; oj++) {
            w0[oj] = Wg_s[(1+h)*GOUT + o0 + oj];
            w1[oj] = Wg_s[(CIN+1+h)*GOUT + o0 + oj];
        }
        #pragma unroll
        for (int bi = 0; bi < 8; bi++) {
            float sv = st_s[h*33 + b0 + bi];
            float pv = P_s[h*33 + b0 + bi];
            #pragma unroll
            for (int oj = 0; oj < 8; oj++)
                acc[bi][oj] = fmaf(sv, w0[oj], fmaf(pv, w1[oj], acc[bi][oj]));
        }
    }
    #pragma unroll
    for (int bi = 0; bi < 8; bi++) {
        int b = b0 + bi;
        #pragma unroll
        for (int oj = 0; oj < 8; oj++) {
            int o = o0 + oj;
            float zr = fast_sigmoid(acc[bi][oj]);
            if (og < 4) {
                float w = zr * st_s[o*33 + b];
                g_zs[(size_t)n*SBH + b*HH + o] = w;
                g_ZT[(size_t)(b*HH + o)*NNODES + n] = __float2half_rn(w);
            } else {
                g_r[(size_t)n*SBH + b*HH + (o - HH)] = zr;
            }
        }
    }
}

// ---------------- update: one warp per node, 4b x 8o per thread ----------------
__global__ __launch_bounds__(32) void update_kernel(const float* __restrict__ src, int t) {
    int n = blockIdx.x, lane = threadIdx.x;
    __shared__ float Wu_s[WU_SZ];
    __shared__ float bu_s[UOUT];
    __shared__ float zs_s[HH*33];
    __shared__ float P2_s[HH*33];
    __shared__ float stt[HH*33];
    __shared__ float rt[HH*33];
    __shared__ float x_s[BB], xp_s[BB];

    const float4* Wu4 = (const float4*)(g_Wu + (size_t)n*WU_SZ);
    for (int j = lane; j < WU_SZ/4; j += 32) ((float4*)Wu_s)[j] = Wu4[j];
    bu_s[lane] = g_bu[n*UOUT + lane];
    for (int j = lane; j < SBH; j += 32) {
        int b = j >> 5, idx = j & 31;
        zs_s[idx*33 + b] = g_zs[(size_t)n*SBH + j];
        float p = 0.f;
        #pragma unroll
        for (int z = 0; z < KSPLIT; z++) p += g_P2[((size_t)z*NNODES + n)*SBH + j];
        P2_s[idx*33 + b] = p;
        stt[idx*33 + b] = g_state[(size_t)n*SBH + j];
        rt[idx*33 + b]  = g_r[(size_t)n*SBH + j];
    }
    x_s[lane] = src[((size_t)lane*TT + t)*NNODES + n];
    {
        float xp = 0.f;
        #pragma unroll
        for (int z = 0; z < KSPLIT; z++)
            xp += g_Xprop[((size_t)z*NNODES + n)*XCOLS + t*BB + lane];
        xp_s[lane] = xp;
    }
    __syncwarp();

    int bg = lane >> 2, og = lane & 3;
    int b0 = bg*4, o0 = og*8;
    float acc[4][8];
    float w0[8], w1[8];
    #pragma unroll
    for (int oj = 0; oj < 8; oj++) {
        w0[oj] = Wu_s[o0 + oj];
        w1[oj] = Wu_s[CIN*UOUT + o0 + oj];
    }
    #pragma unroll
    for (int bi = 0; bi < 4; bi++) {
        float xv = x_s[b0+bi], xpv = xp_s[b0+bi];
        #pragma unroll
        for (int oj = 0; oj < 8; oj++)
            acc[bi][oj] = bu_s[o0+oj] + xv*w0[oj] + xpv*w1[oj];
    }
    for (int h = 0; h < HH; h++) {
        #pragma unroll
        for (int oj = 0; oj < 8; oj++) {
            w0[oj] = Wu_s[(1+h)*UOUT + o0 + oj];
            w1[oj] = Wu_s[(CIN+1+h)*UOUT + o0 + oj];
        }
        #pragma unroll
        for (int bi = 0; bi < 4; bi++) {
            float zv = zs_s[h*33 + b0 + bi];
            float pv = P2_s[h*33 + b0 + bi];
            #pragma unroll
            for (int oj = 0; oj < 8; oj++)
                acc[bi][oj] = fmaf(zv, w0[oj], fmaf(pv, w1[oj], acc[bi][oj]));
        }
    }
    #pragma unroll
    for (int bi = 0; bi < 4; bi++) {
        int b = b0 + bi;
        #pragma unroll
        for (int oj = 0; oj < 8; oj++) {
            int o = o0 + oj;
            float hc = fast_tanh(acc[bi][oj]);
            float r  = rt[o*33 + b];
            float hnew = r * stt[o*33 + b] + (1.f - r) * hc;
            g_state[(size_t)n*SBH + b*HH + o] = hnew;
            g_ST[(size_t)(b*HH + o)*NNODES + n] = __float2half_rn(hnew);
        }
    }
}

// ---------------- end conv ----------------
__global__ __launch_bounds__(256) void out_kernel(
    const float* __restrict__ convW, const float* __restrict__ convb,
    float* __restrict__ out) {
    __shared__ float cw[TT*HH];
    __shared__ float cb[TT];
    int tid = threadIdx.x;
    for (int j = tid; j < TT*HH; j += 256) cw[j] = convW[j];
    if (tid < TT) cb[tid] = convb[tid];
    __syncthreads();
    int gid = blockIdx.x * blockDim.x + tid;
    if (gid >= BB*NNODES) return;
    int b = gid / NNODES, n = gid % NNODES;
    float hreg[HH];
    #pragma unroll
    for (int h = 0; h < HH; h++) hreg[h] = g_state[(size_t)n*SBH + b*HH + h];
    #pragma unroll
    for (int t = 0; t < TT; t++) {
        float a = cb[t];
        #pragma unroll
        for (int h = 0; h < HH; h++) a = fmaf(hreg[h], cw[t*HH + h], a);
        out[(size_t)b*NNODES*TT + n*TT + t] = a;
    }
}

// ---------------- launch ----------------
extern "C" void kernel_launch(void* const* d_in, const int* in_sizes, int n_in,
                              void* d_out, int out_size) {
    const float *src = 0, *E = 0, *gW = 0, *gb = 0, *uW = 0, *ub = 0, *cW = 0, *cb = 0;
    for (int i = 0; i < n_in; i++) {
        const float* p = (const float*)d_in[i];
        switch (in_sizes[i]) {
            case 786432: src = p; break;
            case 20480:  E   = p; break;
            case 42240:  gW  = p; break;
            case 640:    gb  = p; break;
            case 21120:  uW  = p; break;
            case 320:    ub  = p; break;
            case 384:    cW  = p; break;
            case 12:     cb  = p; break;
        }
    }
    float* out = (float*)d_out;

    __half *pAhi, *pAlo, *pXT, *pST, *pZT;
    float *pXprop, *pP, *pP2;
    cudaGetSymbolAddress((void**)&pAhi,  g_Ahi);
    cudaGetSymbolAddress((void**)&pAlo,  g_Alo);
    cudaGetSymbolAddress((void**)&pXT,   g_XT);
    cudaGetSymbolAddress((void**)&pST,   g_ST);
    cudaGetSymbolAddress((void**)&pZT,   g_ZT);
    cudaGetSymbolAddress((void**)&pXprop, g_Xprop);
    cudaGetSymbolAddress((void**)&pP,     g_P);
    cudaGetSymbolAddress((void**)&pP2,    g_P2);

    cudaFuncSetAttribute(mma_gemm, cudaFuncAttributeMaxDynamicSharedMemorySize,
                         SM_TOTAL);

    dim3 gs(SBH/128, NNODES/128, KSPLIT);       // (8, 16, 2) = 256 blocks

    compute_A<<<NNODES, 256>>>(E);                                      // 0
    compute_node_weights<<<NNODES, 256>>>(E, gW, gb, uW, ub);           // 1
    convert_xsrc<<<(XCOLS*NNODES + 255)/256, 256>>>(src);               // 2
    // PROFILING PROBE at launch #3 (= ncu -s 5 target): gate_kernel.
    // Side-effect-safe: writes zs/ZT/r, fully rewritten by real t=0 gate
    // before any consumer. Arbitrates the DRAM-vs-launch-overhead question.
    gate_kernel<<<NNODES, 32>>>(src, 0);                                 // 3 (profiled)
    {
        dim3 g(XCOLS/128, NNODES/128, KSPLIT);  // (3, 16, 2)
        mma_gemm<<<g, 256, SM_TOTAL>>>(pAhi, pAlo, pXT, pXprop, XCOLS); // 4
    }
    init_state<<<(KSPLIT*NNODES*SBH + 255)/256, 256>>>();               // 5

    for (int t = 0; t < TT; t++) {
        if (t > 0)
            mma_gemm<<<gs, 256, SM_TOTAL>>>(pAhi, pAlo, pST, pP, SBH);
        gate_kernel<<<NNODES, 32>>>(src, t);
        if (t > 0)
            mma_gemm<<<gs, 256, SM_TOTAL>>>(pAhi, pAlo, pZT, pP2, SBH);
        update_kernel<<<NNODES, 32>>>(src, t);
    }

    out_kernel<<<(BB*NNODES + 255)/256, 256>>>(cW, cb, out);
}